// round 2
// baseline (speedup 1.0000x reference)
#include <cuda_runtime.h>
#include <cuda_bf16.h>

// Problem constants
#define BATCH 8
#define CH    256
#define CQK   32
#define NQ    4096   // H*W = 64*64

typedef unsigned long long ull;

// ---------------- packed f32x2 helpers (Blackwell FFMA2) ----------------
__device__ __forceinline__ void ffma2(ull& d, ull a, ull b) {
    asm("fma.rn.f32x2 %0, %1, %2, %0;" : "+l"(d) : "l"(a), "l"(b));
}
__device__ __forceinline__ ull mul2(ull a, ull b) {
    ull r; asm("mul.rn.f32x2 %0, %1, %2;" : "=l"(r) : "l"(a), "l"(b)); return r;
}
__device__ __forceinline__ ull pack2(float x, float y) {
    ull r; asm("mov.b64 %0, {%1, %2};" : "=l"(r) : "f"(x), "f"(y)); return r;
}
__device__ __forceinline__ float2 unpack2(ull v) {
    float2 f; asm("mov.b64 {%0, %1}, %2;" : "=f"(f.x), "=f"(f.y) : "l"(v)); return f;
}

// Fast exp on the FMA pipe (avoids MUFU bottleneck). |err| ~3e-6 rel.
__device__ __forceinline__ float fexp(float x) {
    x = fmaxf(x, -87.0f);
    float t = x * 1.4426950408889634f;          // log2(e)
    float z = t + 12582912.0f;                  // round-to-nearest via magic
    int   i = __float_as_int(z) - 0x4B400000;   // integer part
    float r = z - 12582912.0f;
    float f = t - r;                            // frac in [-0.5, 0.5]
    float p = 0.00133336f;
    p = fmaf(p, f, 0.00961813f);
    p = fmaf(p, f, 0.05550411f);
    p = fmaf(p, f, 0.24022651f);
    p = fmaf(p, f, 0.69314718f);
    p = fmaf(p, f, 1.0f);
    float s = __int_as_float((i + 127) << 23);  // 2^i
    return p * s;
}

// ---------------- scratch (no allocation allowed) ----------------
__device__ float g_Q[BATCH * NQ * CQK];   // [b][n][32]
__device__ float g_K[BATCH * NQ * CQK];   // [b][m][32]
__device__ float g_V[BATCH * NQ * CH];    // [b][m][256]

// ---------------- 1x1 conv == per-pixel GEMM ----------------
// out[b][n][o0 + o] = sum_c F[b][c][n] * W[o0+o][c] + bias[o0+o]
// Tile: 64 n x OT o per block, threads = 16 * (OT/4)
template<int OT>
__global__ void conv1x1_kernel(const float* __restrict__ F,
                               const float* __restrict__ W,
                               const float* __restrict__ bias,
                               float* __restrict__ out, int ostride) {
    constexpr int T = 16 * (OT / 4);
    __shared__ float Fs[64][64];       // [c][n]
    __shared__ float Ws[64][OT + 4];   // [c][o] transposed, padded
    const int tid = threadIdx.x;
    const int tx = tid & 15;           // n group (4 each)
    const int ty = tid >> 4;           // o group (4 each)
    const int n0 = blockIdx.x * 64;
    const int o0 = blockIdx.y * OT;
    const int b  = blockIdx.z;
    const float* Fb = F + (size_t)b * CH * NQ;

    float acc[4][4];
#pragma unroll
    for (int i = 0; i < 4; i++)
#pragma unroll
        for (int j = 0; j < 4; j++) acc[i][j] = 0.f;

    for (int c0 = 0; c0 < CH; c0 += 64) {
        // load F tile [64 c][64 n], coalesced
        for (int idx = tid; idx < 1024; idx += T) {
            int r = idx >> 4, c4 = idx & 15;
            *(float4*)&Fs[r][c4 * 4] =
                *(const float4*)&Fb[(size_t)(c0 + r) * NQ + n0 + c4 * 4];
        }
        // load W tile [OT o][64 c], store transposed [c][o]
        for (int idx = tid; idx < OT * 16; idx += T) {
            int o_r = idx >> 4, c4 = idx & 15;
            float4 w4 = *(const float4*)&W[(size_t)(o0 + o_r) * CH + c0 + c4 * 4];
            Ws[c4 * 4 + 0][o_r] = w4.x;
            Ws[c4 * 4 + 1][o_r] = w4.y;
            Ws[c4 * 4 + 2][o_r] = w4.z;
            Ws[c4 * 4 + 3][o_r] = w4.w;
        }
        __syncthreads();
#pragma unroll 8
        for (int cc = 0; cc < 64; cc++) {
            float4 f4 = *(const float4*)&Fs[cc][tx * 4];
            float4 w4 = *(const float4*)&Ws[cc][ty * 4];
            float fa[4] = {f4.x, f4.y, f4.z, f4.w};
            float wa[4] = {w4.x, w4.y, w4.z, w4.w};
#pragma unroll
            for (int i = 0; i < 4; i++)
#pragma unroll
                for (int j = 0; j < 4; j++) acc[i][j] += fa[i] * wa[j];
        }
        __syncthreads();
    }
    float bs[4];
#pragma unroll
    for (int j = 0; j < 4; j++) bs[j] = bias[o0 + ty * 4 + j];
#pragma unroll
    for (int i = 0; i < 4; i++) {
        int n = n0 + tx * 4 + i;
        float4 r = make_float4(acc[i][0] + bs[0], acc[i][1] + bs[1],
                               acc[i][2] + bs[2], acc[i][3] + bs[3]);
        *(float4*)&out[((size_t)b * NQ + n) * ostride + o0 + ty * 4] = r;
    }
}

// ---------------- fused flash attention ----------------
// Block: 64 queries x 256 channels, loop 64-key tiles.
// Thread (ty,tx): q rows = ty*4+i, keys m = tx+16j (S phase), channels = tx*16..+15 (PV phase)
#define SM_QS 0
#define SM_KS 2048            // stride 36
#define SM_VS (2048 + 64*36)  // 4352, stride 256
#define SM_PS (SM_VS + 64*256) // 20736, layout [m][q] stride 68
#define SMEM_FLOATS (SM_PS + 64*68)
#define SMEM_BYTES (SMEM_FLOATS * 4)

__global__ void __launch_bounds__(256, 2)
attn_kernel(const float* __restrict__ Qg, const float* __restrict__ Kg,
            const float* __restrict__ Vg, float* __restrict__ Og) {
    extern __shared__ float sm[];
    float* Qs = sm + SM_QS;
    float* Ks = sm + SM_KS;
    float* Vs = sm + SM_VS;
    float* Ps = sm + SM_PS;

    const int tid = threadIdx.x;
    const int tx = tid & 15;
    const int ty = tid >> 4;
    const int q0 = blockIdx.x * 64;
    const int b  = blockIdx.y;

    // load Q tile once (flat [64][32])
    {
        const float4* qg4 = (const float4*)(Qg + ((size_t)b * NQ + q0) * CQK);
        float4* qs4 = (float4*)Qs;
        for (int idx = tid; idx < 512; idx += 256) qs4[idx] = qg4[idx];
    }

    float m_run[4], l_run[4];
    ull accO[4][8];
#pragma unroll
    for (int i = 0; i < 4; i++) {
        m_run[i] = -1e30f; l_run[i] = 0.f;
#pragma unroll
        for (int k = 0; k < 8; k++) accO[i][k] = 0ULL;
    }

    const float* Kb = Kg + (size_t)b * NQ * CQK;
    const float* Vb = Vg + (size_t)b * NQ * CH;

    for (int kt = 0; kt < NQ / 64; kt++) {
        const int m0 = kt * 64;
        // ---- load K tile (padded stride 36) and V tile (flat) ----
        {
            const float4* kg4 = (const float4*)(Kb + (size_t)m0 * CQK);
            for (int idx = tid; idx < 512; idx += 256) {
                float4 v = kg4[idx];
                int r = idx >> 3, c4 = idx & 7;
                *(float4*)&Ks[r * 36 + c4 * 4] = v;
            }
            const float4* vg4 = (const float4*)(Vb + (size_t)m0 * CH);
            float4* vs4 = (float4*)Vs;
            for (int idx = tid; idx < 4096; idx += 256) vs4[idx] = vg4[idx];
        }
        __syncthreads();

        // ---- S = Q K^T (f32x2 packed over c) ----
        float sreg[4][4];
#pragma unroll
        for (int jp = 0; jp < 2; jp++) {
            ull a2[4][2];
#pragma unroll
            for (int i = 0; i < 4; i++) { a2[i][0] = 0ULL; a2[i][1] = 0ULL; }
#pragma unroll
            for (int c4 = 0; c4 < 8; c4++) {
                ulonglong2 k0 = *(const ulonglong2*)&Ks[(tx + 32 * jp) * 36 + c4 * 4];
                ulonglong2 k1 = *(const ulonglong2*)&Ks[(tx + 32 * jp + 16) * 36 + c4 * 4];
#pragma unroll
                for (int i = 0; i < 4; i++) {
                    ulonglong2 q2 = *(const ulonglong2*)&Qs[(ty * 4 + i) * 32 + c4 * 4];
                    ffma2(a2[i][0], q2.x, k0.x);
                    ffma2(a2[i][0], q2.y, k0.y);
                    ffma2(a2[i][1], q2.x, k1.x);
                    ffma2(a2[i][1], q2.y, k1.y);
                }
            }
#pragma unroll
            for (int i = 0; i < 4; i++) {
                float2 u0 = unpack2(a2[i][0]);
                float2 u1 = unpack2(a2[i][1]);
                sreg[i][2 * jp]     = u0.x + u0.y;
                sreg[i][2 * jp + 1] = u1.x + u1.y;
            }
        }

        // ---- online softmax (per q-row, reduced over 16-lane group) ----
#pragma unroll
        for (int i = 0; i < 4; i++) {
            float tm = fmaxf(fmaxf(sreg[i][0], sreg[i][1]),
                             fmaxf(sreg[i][2], sreg[i][3]));
#pragma unroll
            for (int d = 1; d < 16; d <<= 1)
                tm = fmaxf(tm, __shfl_xor_sync(0xffffffffu, tm, d));
            float mnew = fmaxf(m_run[i], tm);
            float corr = fexp(m_run[i] - mnew);
            m_run[i] = mnew;
            float ps = 0.f;
#pragma unroll
            for (int j = 0; j < 4; j++) {
                float p = fexp(sreg[i][j] - mnew);
                ps += p;
                Ps[(tx + 16 * j) * 68 + ty * 4 + i] = p;   // transposed [m][q]
            }
#pragma unroll
            for (int d = 1; d < 16; d <<= 1)
                ps += __shfl_xor_sync(0xffffffffu, ps, d);
            l_run[i] = l_run[i] * corr + ps;
            ull c2 = pack2(corr, corr);
#pragma unroll
            for (int k = 0; k < 8; k++) accO[i][k] = mul2(accO[i][k], c2);
        }
        __syncthreads();

        // ---- PV: acc[q][c] += p[q][m] * V[m][c] (f32x2 packed over c) ----
#pragma unroll 2
        for (int m = 0; m < 64; m++) {
            float4 p4 = *(const float4*)&Ps[m * 68 + ty * 4];
            ull p2[4];
            p2[0] = pack2(p4.x, p4.x);
            p2[1] = pack2(p4.y, p4.y);
            p2[2] = pack2(p4.z, p4.z);
            p2[3] = pack2(p4.w, p4.w);
            const ulonglong2* vr = (const ulonglong2*)&Vs[m * 256 + tx * 16];
            ulonglong2 va = vr[0], vb2 = vr[1];
#pragma unroll
            for (int i = 0; i < 4; i++) {
                ffma2(accO[i][0], p2[i], va.x);
                ffma2(accO[i][1], p2[i], va.y);
                ffma2(accO[i][2], p2[i], vb2.x);
                ffma2(accO[i][3], p2[i], vb2.y);
            }
            ulonglong2 vc = vr[2], vd = vr[3];
#pragma unroll
            for (int i = 0; i < 4; i++) {
                ffma2(accO[i][4], p2[i], vc.x);
                ffma2(accO[i][5], p2[i], vc.y);
                ffma2(accO[i][6], p2[i], vd.x);
                ffma2(accO[i][7], p2[i], vd.y);
            }
        }
        __syncthreads();
    }

    // ---- epilogue: normalize + store out[b][c][n] ----
    float inv[4];
#pragma unroll
    for (int i = 0; i < 4; i++) inv[i] = 1.0f / l_run[i];
    float* ob = Og + (size_t)b * CH * NQ + q0 + ty * 4;
#pragma unroll
    for (int k = 0; k < 8; k++) {
        float lo[4], hi[4];
#pragma unroll
        for (int i = 0; i < 4; i++) {
            float2 u = unpack2(accO[i][k]);
            lo[i] = u.x * inv[i];
            hi[i] = u.y * inv[i];
        }
        int c = tx * 16 + 2 * k;
        *(float4*)&ob[(size_t)c * NQ]       = make_float4(lo[0], lo[1], lo[2], lo[3]);
        *(float4*)&ob[(size_t)(c + 1) * NQ] = make_float4(hi[0], hi[1], hi[2], hi[3]);
    }
}

// ---------------- launch ----------------
extern "C" void kernel_launch(void* const* d_in, const int* in_sizes, int n_in,
                              void* d_out, int out_size) {
    const float* f1 = (const float*)d_in[0];
    const float* f2 = (const float*)d_in[1];
    const float* f3 = (const float*)d_in[2];
    const float* wq = (const float*)d_in[3];
    const float* bq = (const float*)d_in[4];
    const float* wk = (const float*)d_in[5];
    const float* bk = (const float*)d_in[6];
    const float* wv = (const float*)d_in[7];
    const float* bv = (const float*)d_in[8];
    float* out = (float*)d_out;

    float *qp, *kp, *vp;
    cudaGetSymbolAddress((void**)&qp, g_Q);
    cudaGetSymbolAddress((void**)&kp, g_K);
    cudaGetSymbolAddress((void**)&vp, g_V);

    dim3 gqk(NQ / 64, 1, BATCH);
    conv1x1_kernel<32><<<gqk, 128>>>(f1, wq, bq, qp, CQK);
    conv1x1_kernel<32><<<gqk, 128>>>(f2, wk, bk, kp, CQK);
    dim3 gv(NQ / 64, CH / 64, BATCH);
    conv1x1_kernel<64><<<gv, 256>>>(f3, wv, bv, vp, CH);

    cudaFuncSetAttribute(attn_kernel, cudaFuncAttributeMaxDynamicSharedMemorySize,
                         SMEM_BYTES);
    dim3 ga(NQ / 64, BATCH);
    attn_kernel<<<ga, 256, SMEM_BYTES>>>(qp, kp, vp, out);
}